// round 2
// baseline (speedup 1.0000x reference)
#include <cuda_runtime.h>
#include <math.h>

// Problem constants
constexpr int BATCH = 4;
constexpr int SEQ   = 2048;
constexpr int DIM   = 768;
constexpr int HEADS = 12;
constexpr int DH    = 64;              // head dim
constexpr int MROWS = BATCH * SEQ;     // 8192
constexpr float SCALE = 0.03608439182435161f;  // 768^-0.5

// ---------------------------------------------------------------------------
// Scratch (allocation-free: __device__ globals)
// ---------------------------------------------------------------------------
__device__ __align__(16) float g_q[(size_t)BATCH * HEADS * SEQ * DH];   // 24 MB
__device__ __align__(16) float g_k[(size_t)BATCH * HEADS * SEQ * DH];   // 24 MB
__device__ __align__(16) float g_v[(size_t)BATCH * HEADS * SEQ * DH];   // 24 MB
__device__ __align__(16) float g_att[(size_t)BATCH * SEQ * DIM];        // 24 MB

// ---------------------------------------------------------------------------
// SGEMM tile config: C[M,N] = A[M,K] * B[N,K]^T + bias   (NT, both K-contig)
// ---------------------------------------------------------------------------
constexpr int BM = 128, BN = 128, BK = 8, TM = 8, TN = 8;   // 256 threads

// QKV projection: X[8192,768] * Wqkv[2304,768]^T + b_qkv, scattered into
// q/k/v scratch laid out [b, h, n, d].
__global__ __launch_bounds__(256)
void gemm_qkv_kernel(const float* __restrict__ X, const float* __restrict__ W,
                     const float* __restrict__ bias)
{
    __shared__ float As[BK][BM + 4];
    __shared__ float Bs[BK][BN + 4];
    const int tid = threadIdx.x;
    const int rowBase = blockIdx.y * BM;
    const int colBase = blockIdx.x * BN;
    const int lr = tid >> 1;          // loader row 0..127
    const int lk = (tid & 1) * 4;     // loader k   0 or 4
    const int tr = tid >> 4;          // compute row group 0..15
    const int tc = tid & 15;          // compute col group 0..15

    float acc[TM][TN] = {};
    const float* Aptr = X + (size_t)(rowBase + lr) * DIM + lk;
    const float* Bptr = W + (size_t)(colBase + lr) * DIM + lk;

    float4 a4 = *(const float4*)(Aptr);
    float4 b4 = *(const float4*)(Bptr);

    for (int k0 = 0; k0 < DIM; k0 += BK) {
        As[lk + 0][lr] = a4.x; As[lk + 1][lr] = a4.y;
        As[lk + 2][lr] = a4.z; As[lk + 3][lr] = a4.w;
        Bs[lk + 0][lr] = b4.x; Bs[lk + 1][lr] = b4.y;
        Bs[lk + 2][lr] = b4.z; Bs[lk + 3][lr] = b4.w;
        __syncthreads();
        if (k0 + BK < DIM) {           // prefetch next tile while computing
            a4 = *(const float4*)(Aptr + k0 + BK);
            b4 = *(const float4*)(Bptr + k0 + BK);
        }
        #pragma unroll
        for (int k = 0; k < BK; k++) {
            float a[TM], b[TN];
            #pragma unroll
            for (int i = 0; i < TM; i++) a[i] = As[k][tr * TM + i];
            #pragma unroll
            for (int j = 0; j < TN; j++) b[j] = Bs[k][tc * TN + j];
            #pragma unroll
            for (int i = 0; i < TM; i++)
                #pragma unroll
                for (int j = 0; j < TN; j++)
                    acc[i][j] = fmaf(a[i], b[j], acc[i][j]);
        }
        __syncthreads();
    }

    // Epilogue: scatter into q/k/v in [b, h, n, d] layout.
    // col = which*768 + head*64 + dd  (reshape b n (3 h d))
    #pragma unroll
    for (int i = 0; i < TM; i++) {
        const int row = rowBase + tr * TM + i;
        const int bb = row >> 11;        // / 2048
        const int nn = row & 2047;
        #pragma unroll
        for (int j = 0; j < TN; j++) {
            const int col = colBase + tc * TN + j;
            const float v = acc[i][j] + bias[col];
            const int which = col / DIM;
            const int rem = col - which * DIM;
            const int head = rem >> 6;
            const int dd = rem & 63;
            float* dst = (which == 0) ? g_q : (which == 1) ? g_k : g_v;
            dst[((size_t)((bb * HEADS + head) * SEQ + nn) << 6) + dd] = v;
        }
    }
}

// Output projection: g_att[8192,768] * Wout[768,768]^T + b_out -> out
__global__ __launch_bounds__(256)
void gemm_out_kernel(const float* __restrict__ W, const float* __restrict__ bias,
                     float* __restrict__ out)
{
    __shared__ float As[BK][BM + 4];
    __shared__ float Bs[BK][BN + 4];
    const int tid = threadIdx.x;
    const int rowBase = blockIdx.y * BM;
    const int colBase = blockIdx.x * BN;
    const int lr = tid >> 1;
    const int lk = (tid & 1) * 4;
    const int tr = tid >> 4;
    const int tc = tid & 15;

    float acc[TM][TN] = {};
    const float* Aptr = g_att + (size_t)(rowBase + lr) * DIM + lk;
    const float* Bptr = W + (size_t)(colBase + lr) * DIM + lk;

    float4 a4 = *(const float4*)(Aptr);
    float4 b4 = *(const float4*)(Bptr);

    for (int k0 = 0; k0 < DIM; k0 += BK) {
        As[lk + 0][lr] = a4.x; As[lk + 1][lr] = a4.y;
        As[lk + 2][lr] = a4.z; As[lk + 3][lr] = a4.w;
        Bs[lk + 0][lr] = b4.x; Bs[lk + 1][lr] = b4.y;
        Bs[lk + 2][lr] = b4.z; Bs[lk + 3][lr] = b4.w;
        __syncthreads();
        if (k0 + BK < DIM) {
            a4 = *(const float4*)(Aptr + k0 + BK);
            b4 = *(const float4*)(Bptr + k0 + BK);
        }
        #pragma unroll
        for (int k = 0; k < BK; k++) {
            float a[TM], b[TN];
            #pragma unroll
            for (int i = 0; i < TM; i++) a[i] = As[k][tr * TM + i];
            #pragma unroll
            for (int j = 0; j < TN; j++) b[j] = Bs[k][tc * TN + j];
            #pragma unroll
            for (int i = 0; i < TM; i++)
                #pragma unroll
                for (int j = 0; j < TN; j++)
                    acc[i][j] = fmaf(a[i], b[j], acc[i][j]);
        }
        __syncthreads();
    }

    #pragma unroll
    for (int i = 0; i < TM; i++) {
        const int row = rowBase + tr * TM + i;
        #pragma unroll
        for (int j = 0; j < TN; j++) {
            const int col = colBase + tc * TN + j;
            out[(size_t)row * DIM + col] = acc[i][j] + bias[col];
        }
    }
}

// ---------------------------------------------------------------------------
// Flash attention, fp32. Block: BR=128 query rows of one (b,h); loops over
// all 2048 keys in BC=64 chunks with online softmax.
// Thread layout 16x16; microtile 8 rows x 4 cols.
// ---------------------------------------------------------------------------
constexpr int BR = 128, BC = 64;
constexpr int KST = DH + 1;   // padded K-tile row stride (bank-conflict fix)
constexpr int ATTN_SMEM = (BR * DH + BC * KST + BC * DH + BR * BC) * 4;  // 98560 B

__global__ __launch_bounds__(256)
void attn_kernel()
{
    extern __shared__ float sm[];
    float* Qs = sm;                       // [BR][DH]
    float* Ks = Qs + BR * DH;             // [BC][KST]
    float* Vs = Ks + BC * KST;            // [BC][DH]
    float* Ps = Vs + BC * DH;             // [BR][BC]

    const int bh = blockIdx.x;            // 0..47 = b*12 + h
    const int qt = blockIdx.y;            // 0..15 query tile
    const int tid = threadIdx.x;
    const int tr = tid >> 4;              // 0..15, owns rows 8*tr..+7
    const int tc = tid & 15;              // 0..15, owns cols 4*tc..+3

    const float* Qg = g_q + (size_t)bh * SEQ * DH + (size_t)qt * BR * DH;
    const float* Kg = g_k + (size_t)bh * SEQ * DH;
    const float* Vg = g_v + (size_t)bh * SEQ * DH;

    // Load Q tile, pre-scaled by SCALE
    for (int idx = tid; idx < BR * DH / 4; idx += 256) {
        float4 v = ((const float4*)Qg)[idx];
        v.x *= SCALE; v.y *= SCALE; v.z *= SCALE; v.w *= SCALE;
        ((float4*)Qs)[idx] = v;
    }

    float mrow[8], lrow[8], O[8][4];
    #pragma unroll
    for (int i = 0; i < 8; i++) {
        mrow[i] = -3.0e38f; lrow[i] = 0.f;
        #pragma unroll
        for (int j = 0; j < 4; j++) O[i][j] = 0.f;
    }
    __syncthreads();

    for (int kt = 0; kt < SEQ / BC; kt++) {
        // Load K (padded rows) and V tiles
        const float4* Kg4 = (const float4*)(Kg + (size_t)kt * BC * DH);
        const float4* Vg4 = (const float4*)(Vg + (size_t)kt * BC * DH);
        for (int idx = tid; idx < BC * DH / 4; idx += 256) {
            const int key = idx >> 4;           // 0..63
            const int d4 = (idx & 15) * 4;
            float4 kv = Kg4[idx];
            Ks[key * KST + d4 + 0] = kv.x;
            Ks[key * KST + d4 + 1] = kv.y;
            Ks[key * KST + d4 + 2] = kv.z;
            Ks[key * KST + d4 + 3] = kv.w;
            ((float4*)Vs)[idx] = Vg4[idx];
        }
        __syncthreads();

        // S = Q * K^T (scaled already)
        float s[8][4] = {};
        #pragma unroll 4
        for (int k = 0; k < DH; k++) {
            float a[8], b[4];
            #pragma unroll
            for (int i = 0; i < 8; i++) a[i] = Qs[(tr * 8 + i) * DH + k];
            #pragma unroll
            for (int j = 0; j < 4; j++) b[j] = Ks[(tc * 4 + j) * KST + k];
            #pragma unroll
            for (int i = 0; i < 8; i++)
                #pragma unroll
                for (int j = 0; j < 4; j++)
                    s[i][j] = fmaf(a[i], b[j], s[i][j]);
        }

        // Online softmax. Row r is owned by the 16 lanes sharing tr; they sit
        // in one 16-lane half of a warp, so xor-butterfly over offsets 1..8
        // reduces exactly within the owner group.
        #pragma unroll
        for (int i = 0; i < 8; i++) {
            float mt = fmaxf(fmaxf(s[i][0], s[i][1]), fmaxf(s[i][2], s[i][3]));
            #pragma unroll
            for (int off = 1; off < 16; off <<= 1)
                mt = fmaxf(mt, __shfl_xor_sync(0xffffffffu, mt, off));
            const float mn = fmaxf(mrow[i], mt);
            const float alpha = __expf(mrow[i] - mn);
            mrow[i] = mn;
            float rs = 0.f;
            #pragma unroll
            for (int j = 0; j < 4; j++) {
                const float p = __expf(s[i][j] - mn);
                s[i][j] = p; rs += p;
            }
            #pragma unroll
            for (int off = 1; off < 16; off <<= 1)
                rs += __shfl_xor_sync(0xffffffffu, rs, off);
            lrow[i] = lrow[i] * alpha + rs;
            #pragma unroll
            for (int j = 0; j < 4; j++) O[i][j] *= alpha;
            *(float4*)&Ps[(tr * 8 + i) * BC + tc * 4] =
                make_float4(s[i][0], s[i][1], s[i][2], s[i][3]);
        }
        __syncthreads();

        // O += P * V
        #pragma unroll 4
        for (int kk = 0; kk < BC; kk++) {
            float p[8], vv[4];
            #pragma unroll
            for (int i = 0; i < 8; i++) p[i] = Ps[(tr * 8 + i) * BC + kk];
            #pragma unroll
            for (int j = 0; j < 4; j++) vv[j] = Vs[kk * DH + tc * 4 + j];
            #pragma unroll
            for (int i = 0; i < 8; i++)
                #pragma unroll
                for (int j = 0; j < 4; j++)
                    O[i][j] = fmaf(p[i], vv[j], O[i][j]);
        }
        __syncthreads();
    }

    // Normalize and write to g_att in [b, n, h*d] layout
    const int bb = bh / HEADS;
    const int head = bh % HEADS;
    #pragma unroll
    for (int i = 0; i < 8; i++) {
        const float inv = 1.0f / lrow[i];
        const int nglob = qt * BR + tr * 8 + i;
        float4 o4 = make_float4(O[i][0] * inv, O[i][1] * inv,
                                O[i][2] * inv, O[i][3] * inv);
        *(float4*)&g_att[((size_t)(bb * SEQ + nglob)) * DIM + head * DH + tc * 4] = o4;
    }
}

// ---------------------------------------------------------------------------
// Launch
// ---------------------------------------------------------------------------
extern "C" void kernel_launch(void* const* d_in, const int* in_sizes, int n_in,
                              void* d_out, int out_size)
{
    const float* x     = (const float*)d_in[0];
    const float* w_qkv = (const float*)d_in[1];
    const float* b_qkv = (const float*)d_in[2];
    const float* w_out = (const float*)d_in[3];
    const float* b_out = (const float*)d_in[4];
    float* out = (float*)d_out;

    // One-time host-side config (idempotent; not part of captured work)
    static bool s_configured = false;
    if (!s_configured) {
        cudaFuncSetAttribute(attn_kernel,
                             cudaFuncAttributeMaxDynamicSharedMemorySize, ATTN_SMEM);
        s_configured = true;
    }

    // 1) QKV projection (scattered into [b,h,n,d] scratch)
    dim3 g1(3 * DIM / BN, MROWS / BM);   // (18, 64)
    gemm_qkv_kernel<<<g1, 256>>>(x, w_qkv, b_qkv);

    // 2) Flash attention
    dim3 g2(BATCH * HEADS, SEQ / BR);    // (48, 16)
    attn_kernel<<<g2, 256, ATTN_SMEM>>>();

    // 3) Output projection
    dim3 g3(DIM / BN, MROWS / BM);       // (6, 64)
    gemm_out_kernel<<<g3, 256>>>(w_out, b_out, out);
}

// round 6
// speedup vs baseline: 1.4749x; 1.4749x over previous
#include <cuda_runtime.h>
#include <math.h>
#include <stdint.h>

// Problem constants
constexpr int BATCH = 4;
constexpr int SEQ   = 2048;
constexpr int DIM   = 768;
constexpr int HEADS = 12;
constexpr int DH    = 64;              // head dim
constexpr int MROWS = BATCH * SEQ;     // 8192
constexpr float SCALE = 0.03608439182435161f;  // 768^-0.5

// ---------------------------------------------------------------------------
// Scratch (allocation-free: __device__ globals)
// ---------------------------------------------------------------------------
__device__ __align__(16) float g_q[(size_t)BATCH * HEADS * SEQ * DH];   // 24 MB
__device__ __align__(16) float g_k[(size_t)BATCH * HEADS * SEQ * DH];   // 24 MB
__device__ __align__(16) float g_v[(size_t)BATCH * HEADS * SEQ * DH];   // 24 MB
__device__ __align__(16) float g_att[(size_t)BATCH * SEQ * DIM];        // 24 MB

// ---------------------------------------------------------------------------
// SGEMM tile config: C[M,N] = A[M,K] * B[N,K]^T + bias   (NT, both K-contig)
// EXACTLY the R2 kernels that passed with mem-delta = 0.
// ---------------------------------------------------------------------------
constexpr int BM = 128, BN = 128, BK = 8, TM = 8, TN = 8;   // 256 threads

__global__ __launch_bounds__(256)
void gemm_qkv_kernel(const float* __restrict__ X, const float* __restrict__ W,
                     const float* __restrict__ bias)
{
    __shared__ float As[BK][BM + 4];
    __shared__ float Bs[BK][BN + 4];
    const int tid = threadIdx.x;
    const int rowBase = blockIdx.y * BM;
    const int colBase = blockIdx.x * BN;
    const int lr = tid >> 1;          // loader row 0..127
    const int lk = (tid & 1) * 4;     // loader k   0 or 4
    const int tr = tid >> 4;          // compute row group 0..15
    const int tc = tid & 15;          // compute col group 0..15

    float acc[TM][TN] = {};
    const float* Aptr = X + (size_t)(rowBase + lr) * DIM + lk;
    const float* Bptr = W + (size_t)(colBase + lr) * DIM + lk;

    float4 a4 = *(const float4*)(Aptr);
    float4 b4 = *(const float4*)(Bptr);

    for (int k0 = 0; k0 < DIM; k0 += BK) {
        As[lk + 0][lr] = a4.x; As[lk + 1][lr] = a4.y;
        As[lk + 2][lr] = a4.z; As[lk + 3][lr] = a4.w;
        Bs[lk + 0][lr] = b4.x; Bs[lk + 1][lr] = b4.y;
        Bs[lk + 2][lr] = b4.z; Bs[lk + 3][lr] = b4.w;
        __syncthreads();
        if (k0 + BK < DIM) {           // prefetch next tile while computing
            a4 = *(const float4*)(Aptr + k0 + BK);
            b4 = *(const float4*)(Bptr + k0 + BK);
        }
        #pragma unroll
        for (int k = 0; k < BK; k++) {
            float a[TM], b[TN];
            #pragma unroll
            for (int i = 0; i < TM; i++) a[i] = As[k][tr * TM + i];
            #pragma unroll
            for (int j = 0; j < TN; j++) b[j] = Bs[k][tc * TN + j];
            #pragma unroll
            for (int i = 0; i < TM; i++)
                #pragma unroll
                for (int j = 0; j < TN; j++)
                    acc[i][j] = fmaf(a[i], b[j], acc[i][j]);
        }
        __syncthreads();
    }

    // Epilogue: scatter into q/k/v in [b, h, n, d] layout.
    #pragma unroll
    for (int i = 0; i < TM; i++) {
        const int row = rowBase + tr * TM + i;
        const int bb = row >> 11;        // / 2048
        const int nn = row & 2047;
        #pragma unroll
        for (int j = 0; j < TN; j++) {
            const int col = colBase + tc * TN + j;
            const float v = acc[i][j] + bias[col];
            const int which = col / DIM;
            const int rem = col - which * DIM;
            const int head = rem >> 6;
            const int dd = rem & 63;
            float* dst = (which == 0) ? g_q : (which == 1) ? g_k : g_v;
            dst[((size_t)((bb * HEADS + head) * SEQ + nn) << 6) + dd] = v;
        }
    }
}

__global__ __launch_bounds__(256)
void gemm_out_kernel(const float* __restrict__ W, const float* __restrict__ bias,
                     float* __restrict__ out)
{
    __shared__ float As[BK][BM + 4];
    __shared__ float Bs[BK][BN + 4];
    const int tid = threadIdx.x;
    const int rowBase = blockIdx.y * BM;
    const int colBase = blockIdx.x * BN;
    const int lr = tid >> 1;
    const int lk = (tid & 1) * 4;
    const int tr = tid >> 4;
    const int tc = tid & 15;

    float acc[TM][TN] = {};
    const float* Aptr = g_att + (size_t)(rowBase + lr) * DIM + lk;
    const float* Bptr = W + (size_t)(colBase + lr) * DIM + lk;

    float4 a4 = *(const float4*)(Aptr);
    float4 b4 = *(const float4*)(Bptr);

    for (int k0 = 0; k0 < DIM; k0 += BK) {
        As[lk + 0][lr] = a4.x; As[lk + 1][lr] = a4.y;
        As[lk + 2][lr] = a4.z; As[lk + 3][lr] = a4.w;
        Bs[lk + 0][lr] = b4.x; Bs[lk + 1][lr] = b4.y;
        Bs[lk + 2][lr] = b4.z; Bs[lk + 3][lr] = b4.w;
        __syncthreads();
        if (k0 + BK < DIM) {
            a4 = *(const float4*)(Aptr + k0 + BK);
            b4 = *(const float4*)(Bptr + k0 + BK);
        }
        #pragma unroll
        for (int k = 0; k < BK; k++) {
            float a[TM], b[TN];
            #pragma unroll
            for (int i = 0; i < TM; i++) a[i] = As[k][tr * TM + i];
            #pragma unroll
            for (int j = 0; j < TN; j++) b[j] = Bs[k][tc * TN + j];
            #pragma unroll
            for (int i = 0; i < TM; i++)
                #pragma unroll
                for (int j = 0; j < TN; j++)
                    acc[i][j] = fmaf(a[i], b[j], acc[i][j]);
        }
        __syncthreads();
    }

    #pragma unroll
    for (int i = 0; i < TM; i++) {
        const int row = rowBase + tr * TM + i;
        #pragma unroll
        for (int j = 0; j < TN; j++) {
            const int col = colBase + tc * TN + j;
            out[(size_t)row * DIM + col] = acc[i][j] + bias[col];
        }
    }
}

// ---------------------------------------------------------------------------
// tf32 helpers (scalar-reference interface; no pointers into local arrays)
// ---------------------------------------------------------------------------
__device__ __forceinline__ uint32_t cvt_tf32(float f) {
    uint32_t r;
    asm("cvt.rna.tf32.f32 %0, %1;" : "=r"(r) : "f"(f));
    return r;
}

__device__ __forceinline__ void mma8(float& c0, float& c1, float& c2, float& c3,
                                     uint32_t a0, uint32_t a1, uint32_t a2, uint32_t a3,
                                     uint32_t b0, uint32_t b1) {
    asm volatile(
        "mma.sync.aligned.m16n8k8.row.col.f32.tf32.tf32.f32 "
        "{%0,%1,%2,%3}, {%4,%5,%6,%7}, {%8,%9}, {%0,%1,%2,%3};\n"
        : "+f"(c0), "+f"(c1), "+f"(c2), "+f"(c3)
        : "r"(a0), "r"(a1), "r"(a2), "r"(a3), "r"(b0), "r"(b1));
}

// ---------------------------------------------------------------------------
// Flash attention, tf32 mma. Block = 128 q-rows of one (b,h); 8 warps, each
// warp owns 16 full rows. Keys in chunks of 64 with online softmax.
// ---------------------------------------------------------------------------
constexpr int BC = 64;
constexpr int AST = 68;   // smem row stride: conflict-free for fragment loads
constexpr int ATTN_SMEM = (128 + 64 + 64 + 128) * AST * 4;   // 104448 B

__global__ __launch_bounds__(256)
void attn_kernel()
{
    extern __shared__ uint32_t smu[];
    uint32_t* QS = smu;                 // [128][AST]
    uint32_t* KS = QS + 128 * AST;      // [64][AST]
    uint32_t* VS = KS + 64 * AST;       // [64][AST]
    uint32_t* PS = VS + 64 * AST;       // [128][AST]

    const int bh = blockIdx.x;
    const int qt = blockIdx.y;
    const int tid = threadIdx.x;
    const int lane = tid & 31;
    const int gid = lane >> 2, tig = lane & 3;
    const int w = tid >> 5;
    const int rb = w * 16;              // warp's q-row base within tile

    const float* Qg = g_q + (size_t)bh * SEQ * DH + (size_t)qt * 128 * DH;
    const float* Kg = g_k + (size_t)bh * SEQ * DH;
    const float* Vg = g_v + (size_t)bh * SEQ * DH;

    // Load + scale + tf32-convert Q tile
    for (int idx = tid; idx < 128 * DH / 4; idx += 256) {
        const int row = idx >> 4, c4 = (idx & 15) * 4;
        float4 v = ((const float4*)Qg)[idx];
        QS[row * AST + c4 + 0] = cvt_tf32(v.x * SCALE);
        QS[row * AST + c4 + 1] = cvt_tf32(v.y * SCALE);
        QS[row * AST + c4 + 2] = cvt_tf32(v.z * SCALE);
        QS[row * AST + c4 + 3] = cvt_tf32(v.w * SCALE);
    }

    float4 o[8];
    #pragma unroll
    for (int j = 0; j < 8; j++) o[j] = make_float4(0.f, 0.f, 0.f, 0.f);
    float m0 = -3.0e38f, m1 = -3.0e38f;
    float l0 = 0.f, l1 = 0.f;

    for (int kt = 0; kt < SEQ / BC; kt++) {
        __syncthreads();                 // prev PV reads done before overwrite
        const float4* Kg4 = (const float4*)(Kg + (size_t)kt * BC * DH);
        const float4* Vg4 = (const float4*)(Vg + (size_t)kt * BC * DH);
        for (int idx = tid; idx < BC * DH / 4; idx += 256) {
            const int key = idx >> 4, c4 = (idx & 15) * 4;
            float4 kv = Kg4[idx], vv = Vg4[idx];
            KS[key * AST + c4 + 0] = cvt_tf32(kv.x);
            KS[key * AST + c4 + 1] = cvt_tf32(kv.y);
            KS[key * AST + c4 + 2] = cvt_tf32(kv.z);
            KS[key * AST + c4 + 3] = cvt_tf32(kv.w);
            VS[key * AST + c4 + 0] = cvt_tf32(vv.x);
            VS[key * AST + c4 + 1] = cvt_tf32(vv.y);
            VS[key * AST + c4 + 2] = cvt_tf32(vv.z);
            VS[key * AST + c4 + 3] = cvt_tf32(vv.w);
        }
        __syncthreads();

        // S = Q * K^T  (warp: 16 rows x 64 keys, 8 n-tiles)
        float4 s[8];
        #pragma unroll
        for (int j = 0; j < 8; j++) s[j] = make_float4(0.f, 0.f, 0.f, 0.f);
        #pragma unroll
        for (int kk = 0; kk < DH; kk += 8) {
            const int i0 = (rb + gid) * AST + kk + tig;
            const int i1 = (rb + gid + 8) * AST + kk + tig;
            const uint32_t a0 = QS[i0], a1 = QS[i1];
            const uint32_t a2 = QS[i0 + 4], a3 = QS[i1 + 4];
            #pragma unroll
            for (int j = 0; j < 8; j++) {
                const int bi = (j * 8 + gid) * AST + kk + tig;
                mma8(s[j].x, s[j].y, s[j].z, s[j].w,
                     a0, a1, a2, a3, KS[bi], KS[bi + 4]);
            }
        }

        // Online softmax (rows gid and gid+8; reduce over 4-lane tig group)
        float mt0 = -3.0e38f, mt1 = -3.0e38f;
        #pragma unroll
        for (int j = 0; j < 8; j++) {
            mt0 = fmaxf(mt0, fmaxf(s[j].x, s[j].y));
            mt1 = fmaxf(mt1, fmaxf(s[j].z, s[j].w));
        }
        mt0 = fmaxf(mt0, __shfl_xor_sync(0xffffffffu, mt0, 1));
        mt0 = fmaxf(mt0, __shfl_xor_sync(0xffffffffu, mt0, 2));
        mt1 = fmaxf(mt1, __shfl_xor_sync(0xffffffffu, mt1, 1));
        mt1 = fmaxf(mt1, __shfl_xor_sync(0xffffffffu, mt1, 2));
        const float mn0 = fmaxf(m0, mt0), mn1 = fmaxf(m1, mt1);
        const float al0 = __expf(m0 - mn0), al1 = __expf(m1 - mn1);
        m0 = mn0; m1 = mn1;

        float rs0 = 0.f, rs1 = 0.f;
        const int p0base = (rb + gid) * AST + tig * 2;
        const int p1base = (rb + gid + 8) * AST + tig * 2;
        #pragma unroll
        for (int j = 0; j < 8; j++) {
            const float e0 = __expf(s[j].x - mn0);
            const float e1 = __expf(s[j].y - mn0);
            const float e2 = __expf(s[j].z - mn1);
            const float e3 = __expf(s[j].w - mn1);
            rs0 += e0 + e1; rs1 += e2 + e3;
            PS[p0base + j * 8 + 0] = cvt_tf32(e0);
            PS[p0base + j * 8 + 1] = cvt_tf32(e1);
            PS[p1base + j * 8 + 0] = cvt_tf32(e2);
            PS[p1base + j * 8 + 1] = cvt_tf32(e3);
        }
        rs0 += __shfl_xor_sync(0xffffffffu, rs0, 1);
        rs0 += __shfl_xor_sync(0xffffffffu, rs0, 2);
        rs1 += __shfl_xor_sync(0xffffffffu, rs1, 1);
        rs1 += __shfl_xor_sync(0xffffffffu, rs1, 2);
        l0 = l0 * al0 + rs0;
        l1 = l1 * al1 + rs1;

        #pragma unroll
        for (int j = 0; j < 8; j++) {
            o[j].x *= al0; o[j].y *= al0;
            o[j].z *= al1; o[j].w *= al1;
        }
        __syncwarp();

        // O += P * V  (k over 64 keys, 8 d-tiles)
        #pragma unroll
        for (int kk = 0; kk < BC; kk += 8) {
            const int i0 = (rb + gid) * AST + kk + tig;
            const int i1 = (rb + gid + 8) * AST + kk + tig;
            const uint32_t a0 = PS[i0], a1 = PS[i1];
            const uint32_t a2 = PS[i0 + 4], a3 = PS[i1 + 4];
            #pragma unroll
            for (int j = 0; j < 8; j++) {
                mma8(o[j].x, o[j].y, o[j].z, o[j].w,
                     a0, a1, a2, a3,
                     VS[(kk + tig) * AST + j * 8 + gid],
                     VS[(kk + tig + 4) * AST + j * 8 + gid]);
            }
        }
    }

    // Normalize + write to g_att [b, n, h*d]
    const int bb = bh / HEADS;
    const int head = bh % HEADS;
    const float inv0 = 1.0f / l0, inv1 = 1.0f / l1;
    const int n0 = qt * 128 + rb + gid;
    const int n1 = n0 + 8;
    float* dst0 = g_att + (size_t)(bb * SEQ + n0) * DIM + head * DH;
    float* dst1 = g_att + (size_t)(bb * SEQ + n1) * DIM + head * DH;
    #pragma unroll
    for (int j = 0; j < 8; j++) {
        const int col = j * 8 + tig * 2;
        dst0[col + 0] = o[j].x * inv0;
        dst0[col + 1] = o[j].y * inv0;
        dst1[col + 0] = o[j].z * inv1;
        dst1[col + 1] = o[j].w * inv1;
    }
}

// ---------------------------------------------------------------------------
// Launch (R2 structure: unguarded attribute set, proven capture-safe)
// ---------------------------------------------------------------------------
extern "C" void kernel_launch(void* const* d_in, const int* in_sizes, int n_in,
                              void* d_out, int out_size)
{
    const float* x     = (const float*)d_in[0];
    const float* w_qkv = (const float*)d_in[1];
    const float* b_qkv = (const float*)d_in[2];
    const float* w_out = (const float*)d_in[3];
    const float* b_out = (const float*)d_in[4];
    float* out = (float*)d_out;

    cudaFuncSetAttribute(attn_kernel,
                         cudaFuncAttributeMaxDynamicSharedMemorySize, ATTN_SMEM);

    // 1) QKV projection (scattered into [b,h,n,d] scratch)
    dim3 g1(3 * DIM / BN, MROWS / BM);   // (18, 64)
    gemm_qkv_kernel<<<g1, 256>>>(x, w_qkv, b_qkv);

    // 2) Flash attention (tf32 tensor cores)
    dim3 g2(BATCH * HEADS, SEQ / 128);   // (48, 16)
    attn_kernel<<<g2, 256, ATTN_SMEM>>>();

    // 3) Output projection
    dim3 g3(DIM / BN, MROWS / BM);       // (6, 64)
    gemm_out_kernel<<<g3, 256>>>(w_out, b_out, out);
}

// round 9
// speedup vs baseline: 1.8812x; 1.2755x over previous
#include <cuda_runtime.h>
#include <math.h>
#include <stdint.h>

// Problem constants
constexpr int BATCH = 4;
constexpr int SEQ   = 2048;
constexpr int DIM   = 768;
constexpr int HEADS = 12;
constexpr int DH    = 64;              // head dim
constexpr int MROWS = BATCH * SEQ;     // 8192
constexpr float SCALE = 0.03608439182435161f;  // 768^-0.5

// ---------------------------------------------------------------------------
// Scratch (allocation-free: __device__ globals)
// ---------------------------------------------------------------------------
__device__ __align__(16) float g_q[(size_t)BATCH * HEADS * SEQ * DH];
__device__ __align__(16) float g_k[(size_t)BATCH * HEADS * SEQ * DH];
__device__ __align__(16) float g_v[(size_t)BATCH * HEADS * SEQ * DH];
__device__ __align__(16) float g_att[(size_t)BATCH * SEQ * DIM];

// ---------------------------------------------------------------------------
// Conversion helpers
// ---------------------------------------------------------------------------
__device__ __forceinline__ uint32_t cvt_tf32(float f) {
    uint32_t r;
    asm("cvt.rna.tf32.f32 %0, %1;" : "=r"(r) : "f"(f));
    return r;
}

// pack two floats to bf16x2 word: f0 -> low half, f1 -> high half
__device__ __forceinline__ uint32_t cvt2_bf16(float f0, float f1) {
    uint32_t r;
    asm("cvt.rn.bf16x2.f32 %0, %2, %1;" : "=r"(r) : "f"(f0), "f"(f1));
    return r;
}
__device__ __forceinline__ float bf16lo_f(uint32_t w) { return __uint_as_float(w << 16); }
__device__ __forceinline__ float bf16hi_f(uint32_t w) { return __uint_as_float(w & 0xffff0000u); }

// tf32 m16n8k8 mma (attention)
__device__ __forceinline__ void mma8(float& c0, float& c1, float& c2, float& c3,
                                     uint32_t a0, uint32_t a1, uint32_t a2, uint32_t a3,
                                     uint32_t b0, uint32_t b1) {
    asm volatile(
        "mma.sync.aligned.m16n8k8.row.col.f32.tf32.tf32.f32 "
        "{%0,%1,%2,%3}, {%4,%5,%6,%7}, {%8,%9}, {%0,%1,%2,%3};\n"
        : "+f"(c0), "+f"(c1), "+f"(c2), "+f"(c3)
        : "r"(a0), "r"(a1), "r"(a2), "r"(a3), "r"(b0), "r"(b1));
}

// bf16 m16n8k16 mma (projections)
__device__ __forceinline__ void mma16(float& c0, float& c1, float& c2, float& c3,
                                      uint32_t a0, uint32_t a1, uint32_t a2, uint32_t a3,
                                      uint32_t b0, uint32_t b1) {
    asm volatile(
        "mma.sync.aligned.m16n8k16.row.col.f32.bf16.bf16.f32 "
        "{%0,%1,%2,%3}, {%4,%5,%6,%7}, {%8,%9}, {%0,%1,%2,%3};\n"
        : "+f"(c0), "+f"(c1), "+f"(c2), "+f"(c3)
        : "r"(a0), "r"(a1), "r"(a2), "r"(a3), "r"(b0), "r"(b1));
}

// scatter one QKV element into g_q/g_k/g_v ([b,h,n,d] layout)
__device__ __forceinline__ void scatter_qkv(float v, int row, int col) {
    const int bb = row >> 11, nn = row & 2047;
    const int which = col / DIM;
    const int rem = col - which * DIM;
    const int head = rem >> 6, dd = rem & 63;
    float* dst = (which == 0) ? g_q : (which == 1) ? g_k : g_v;
    dst[((size_t)((bb * HEADS + head) * SEQ + nn) << 6) + dd] = v;
}

// ---------------------------------------------------------------------------
// Split-bf16 (3-term) GEMM bodies. Block 128x64, BK=16, 256 threads,
// 8 warps as 4M x 2N, warp tile 32x32. acc = 8 float4/thread.
// NON-TEMPLATED: two standalone kernels (qkv scatter / plain store).
// smem words are bf16x2 k-pairs; 8 words per 16-k row, stride 9.
// ---------------------------------------------------------------------------
constexpr int WST = 9;

__global__ __launch_bounds__(256)
void gemm_qkv_bf16(const float* __restrict__ A, const float* __restrict__ W,
                   const float* __restrict__ bias)
{
    __shared__ uint32_t AhS[128 * WST], AlS[128 * WST];
    __shared__ uint32_t BhS[64 * WST],  BlS[64 * WST];

    const int tid = threadIdx.x;
    const int lane = tid & 31;
    const int gid = lane >> 2, tig = lane & 3;
    const int w = tid >> 5;
    const int wm = w >> 1;
    const int wn = w & 1;
    const int rowBase = blockIdx.y * 128;
    const int colBase = blockIdx.x * 64;

    const int l_row  = tid >> 1;
    const int l_kf   = (tid & 1) * 8;
    const int l_rowB = tid >> 2;
    const int l_kfB  = (tid & 3) * 4;

    float4 acc[8];
    #pragma unroll
    for (int t = 0; t < 8; t++) acc[t] = make_float4(0.f, 0.f, 0.f, 0.f);

    const float* Aptr = A + (size_t)(rowBase + l_row) * DIM + l_kf;
    const float* Bptr = W + (size_t)(colBase + l_rowB) * DIM + l_kfB;

    float4 pa0 = *(const float4*)(Aptr);
    float4 pa1 = *(const float4*)(Aptr + 4);
    float4 pb0 = *(const float4*)(Bptr);

    for (int k0 = 0; k0 < DIM; k0 += 16) {
        {
            const int base = l_row * WST + (l_kf >> 1);
            uint32_t h;
            h = cvt2_bf16(pa0.x, pa0.y); AhS[base + 0] = h;
            AlS[base + 0] = cvt2_bf16(pa0.x - bf16lo_f(h), pa0.y - bf16hi_f(h));
            h = cvt2_bf16(pa0.z, pa0.w); AhS[base + 1] = h;
            AlS[base + 1] = cvt2_bf16(pa0.z - bf16lo_f(h), pa0.w - bf16hi_f(h));
            h = cvt2_bf16(pa1.x, pa1.y); AhS[base + 2] = h;
            AlS[base + 2] = cvt2_bf16(pa1.x - bf16lo_f(h), pa1.y - bf16hi_f(h));
            h = cvt2_bf16(pa1.z, pa1.w); AhS[base + 3] = h;
            AlS[base + 3] = cvt2_bf16(pa1.z - bf16lo_f(h), pa1.w - bf16hi_f(h));
        }
        {
            const int base = l_rowB * WST + (l_kfB >> 1);
            uint32_t h;
            h = cvt2_bf16(pb0.x, pb0.y); BhS[base + 0] = h;
            BlS[base + 0] = cvt2_bf16(pb0.x - bf16lo_f(h), pb0.y - bf16hi_f(h));
            h = cvt2_bf16(pb0.z, pb0.w); BhS[base + 1] = h;
            BlS[base + 1] = cvt2_bf16(pb0.z - bf16lo_f(h), pb0.w - bf16hi_f(h));
        }
        __syncthreads();
        if (k0 + 16 < DIM) {
            pa0 = *(const float4*)(Aptr + k0 + 16);
            pa1 = *(const float4*)(Aptr + k0 + 20);
            pb0 = *(const float4*)(Bptr + k0 + 16);
        }
        #pragma unroll
        for (int i = 0; i < 2; i++) {
            const int r0 = (wm * 32 + i * 16 + gid) * WST + tig;
            const int r1 = (wm * 32 + i * 16 + gid + 8) * WST + tig;
            const uint32_t ah0 = AhS[r0], ah1 = AhS[r1];
            const uint32_t ah2 = AhS[r0 + 4], ah3 = AhS[r1 + 4];
            const uint32_t al0 = AlS[r0], al1 = AlS[r1];
            const uint32_t al2 = AlS[r0 + 4], al3 = AlS[r1 + 4];
            #pragma unroll
            for (int j = 0; j < 4; j++) {
                const int cb = (wn * 32 + j * 8 + gid) * WST + tig;
                const uint32_t bh0 = BhS[cb], bh1 = BhS[cb + 4];
                const uint32_t bl0 = BlS[cb], bl1 = BlS[cb + 4];
                const int t = i * 4 + j;
                mma16(acc[t].x, acc[t].y, acc[t].z, acc[t].w,
                      ah0, ah1, ah2, ah3, bh0, bh1);
                mma16(acc[t].x, acc[t].y, acc[t].z, acc[t].w,
                      ah0, ah1, ah2, ah3, bl0, bl1);
                mma16(acc[t].x, acc[t].y, acc[t].z, acc[t].w,
                      al0, al1, al2, al3, bh0, bh1);
            }
        }
        __syncthreads();
    }

    #pragma unroll
    for (int i = 0; i < 2; i++) {
        const int r0 = rowBase + wm * 32 + i * 16 + gid;
        #pragma unroll
        for (int j = 0; j < 4; j++) {
            const int t = i * 4 + j;
            const int c0 = colBase + wn * 32 + j * 8 + tig * 2;
            const float b0v = bias[c0], b1v = bias[c0 + 1];
            scatter_qkv(acc[t].x + b0v, r0,     c0);
            scatter_qkv(acc[t].y + b1v, r0,     c0 + 1);
            scatter_qkv(acc[t].z + b0v, r0 + 8, c0);
            scatter_qkv(acc[t].w + b1v, r0 + 8, c0 + 1);
        }
    }
}

__global__ __launch_bounds__(256)
void gemm_out_bf16(const float* __restrict__ W, const float* __restrict__ bias,
                   float* __restrict__ out)
{
    __shared__ uint32_t AhS[128 * WST], AlS[128 * WST];
    __shared__ uint32_t BhS[64 * WST],  BlS[64 * WST];

    const int tid = threadIdx.x;
    const int lane = tid & 31;
    const int gid = lane >> 2, tig = lane & 3;
    const int w = tid >> 5;
    const int wm = w >> 1;
    const int wn = w & 1;
    const int rowBase = blockIdx.y * 128;
    const int colBase = blockIdx.x * 64;

    const int l_row  = tid >> 1;
    const int l_kf   = (tid & 1) * 8;
    const int l_rowB = tid >> 2;
    const int l_kfB  = (tid & 3) * 4;

    float4 acc[8];
    #pragma unroll
    for (int t = 0; t < 8; t++) acc[t] = make_float4(0.f, 0.f, 0.f, 0.f);

    const float* Aptr = g_att + (size_t)(rowBase + l_row) * DIM + l_kf;
    const float* Bptr = W + (size_t)(colBase + l_rowB) * DIM + l_kfB;

    float4 pa0 = *(const float4*)(Aptr);
    float4 pa1 = *(const float4*)(Aptr + 4);
    float4 pb0 = *(const float4*)(Bptr);

    for (int k0 = 0; k0 < DIM; k0 += 16) {
        {
            const int base = l_row * WST + (l_kf >> 1);
            uint32_t h;
            h = cvt2_bf16(pa0.x, pa0.y); AhS[base + 0] = h;
            AlS[base + 0] = cvt2_bf16(pa0.x - bf16lo_f(h), pa0.y - bf16hi_f(h));
            h = cvt2_bf16(pa0.z, pa0.w); AhS[base + 1] = h;
            AlS[base + 1] = cvt2_bf16(pa0.z - bf16lo_f(h), pa0.w - bf16hi_f(h));
            h = cvt2_bf16(pa1.x, pa1.y); AhS[base + 2] = h;
            AlS[base + 2] = cvt2_bf16(pa1.x - bf16lo_f(h), pa1.y - bf16hi_f(h));
            h = cvt2_bf16(pa1.z, pa1.w); AhS[base + 3] = h;
            AlS[base + 3] = cvt2_bf16(pa1.z - bf16lo_f(h), pa1.w - bf16hi_f(h));
        }
        {
            const int base = l_rowB * WST + (l_kfB >> 1);
            uint32_t h;
            h = cvt2_bf16(pb0.x, pb0.y); BhS[base + 0] = h;
            BlS[base + 0] = cvt2_bf16(pb0.x - bf16lo_f(h), pb0.y - bf16hi_f(h));
            h = cvt2_bf16(pb0.z, pb0.w); BhS[base + 1] = h;
            BlS[base + 1] = cvt2_bf16(pb0.z - bf16lo_f(h), pb0.w - bf16hi_f(h));
        }
        __syncthreads();
        if (k0 + 16 < DIM) {
            pa0 = *(const float4*)(Aptr + k0 + 16);
            pa1 = *(const float4*)(Aptr + k0 + 20);
            pb0 = *(const float4*)(Bptr + k0 + 16);
        }
        #pragma unroll
        for (int i = 0; i < 2; i++) {
            const int r0 = (wm * 32 + i * 16 + gid) * WST + tig;
            const int r1 = (wm * 32 + i * 16 + gid + 8) * WST + tig;
            const uint32_t ah0 = AhS[r0], ah1 = AhS[r1];
            const uint32_t ah2 = AhS[r0 + 4], ah3 = AhS[r1 + 4];
            const uint32_t al0 = AlS[r0], al1 = AlS[r1];
            const uint32_t al2 = AlS[r0 + 4], al3 = AlS[r1 + 4];
            #pragma unroll
            for (int j = 0; j < 4; j++) {
                const int cb = (wn * 32 + j * 8 + gid) * WST + tig;
                const uint32_t bh0 = BhS[cb], bh1 = BhS[cb + 4];
                const uint32_t bl0 = BlS[cb], bl1 = BlS[cb + 4];
                const int t = i * 4 + j;
                mma16(acc[t].x, acc[t].y, acc[t].z, acc[t].w,
                      ah0, ah1, ah2, ah3, bh0, bh1);
                mma16(acc[t].x, acc[t].y, acc[t].z, acc[t].w,
                      ah0, ah1, ah2, ah3, bl0, bl1);
                mma16(acc[t].x, acc[t].y, acc[t].z, acc[t].w,
                      al0, al1, al2, al3, bh0, bh1);
            }
        }
        __syncthreads();
    }

    #pragma unroll
    for (int i = 0; i < 2; i++) {
        const int r0 = rowBase + wm * 32 + i * 16 + gid;
        #pragma unroll
        for (int j = 0; j < 4; j++) {
            const int t = i * 4 + j;
            const int c0 = colBase + wn * 32 + j * 8 + tig * 2;
            const float b0v = bias[c0], b1v = bias[c0 + 1];
            out[(size_t)r0 * DIM + c0]           = acc[t].x + b0v;
            out[(size_t)r0 * DIM + c0 + 1]       = acc[t].y + b1v;
            out[(size_t)(r0 + 8) * DIM + c0]     = acc[t].z + b0v;
            out[(size_t)(r0 + 8) * DIM + c0 + 1] = acc[t].w + b1v;
        }
    }
}

// ---------------------------------------------------------------------------
// Flash attention, tf32 mma (UNCHANGED from passing R6 kernel).
// ---------------------------------------------------------------------------
constexpr int BC = 64;
constexpr int AST = 68;
constexpr int ATTN_SMEM = (128 + 64 + 64 + 128) * AST * 4;   // 104448 B

__global__ __launch_bounds__(256)
void attn_kernel()
{
    extern __shared__ uint32_t smu[];
    uint32_t* QS = smu;                 // [128][AST]
    uint32_t* KS = QS + 128 * AST;      // [64][AST]
    uint32_t* VS = KS + 64 * AST;       // [64][AST]
    uint32_t* PS = VS + 64 * AST;       // [128][AST]

    const int bh = blockIdx.x;
    const int qt = blockIdx.y;
    const int tid = threadIdx.x;
    const int lane = tid & 31;
    const int gid = lane >> 2, tig = lane & 3;
    const int w = tid >> 5;
    const int rb = w * 16;

    const float* Qg = g_q + (size_t)bh * SEQ * DH + (size_t)qt * 128 * DH;
    const float* Kg = g_k + (size_t)bh * SEQ * DH;
    const float* Vg = g_v + (size_t)bh * SEQ * DH;

    for (int idx = tid; idx < 128 * DH / 4; idx += 256) {
        const int row = idx >> 4, c4 = (idx & 15) * 4;
        float4 v = ((const float4*)Qg)[idx];
        QS[row * AST + c4 + 0] = cvt_tf32(v.x * SCALE);
        QS[row * AST + c4 + 1] = cvt_tf32(v.y * SCALE);
        QS[row * AST + c4 + 2] = cvt_tf32(v.z * SCALE);
        QS[row * AST + c4 + 3] = cvt_tf32(v.w * SCALE);
    }

    float4 o[8];
    #pragma unroll
    for (int j = 0; j < 8; j++) o[j] = make_float4(0.f, 0.f, 0.f, 0.f);
    float m0 = -3.0e38f, m1 = -3.0e38f;
    float l0 = 0.f, l1 = 0.f;

    for (int kt = 0; kt < SEQ / BC; kt++) {
        __syncthreads();
        const float4* Kg4 = (const float4*)(Kg + (size_t)kt * BC * DH);
        const float4* Vg4 = (const float4*)(Vg + (size_t)kt * BC * DH);
        for (int idx = tid; idx < BC * DH / 4; idx += 256) {
            const int key = idx >> 4, c4 = (idx & 15) * 4;
            float4 kv = Kg4[idx], vv = Vg4[idx];
            KS[key * AST + c4 + 0] = cvt_tf32(kv.x);
            KS[key * AST + c4 + 1] = cvt_tf32(kv.y);
            KS[key * AST + c4 + 2] = cvt_tf32(kv.z);
            KS[key * AST + c4 + 3] = cvt_tf32(kv.w);
            VS[key * AST + c4 + 0] = cvt_tf32(vv.x);
            VS[key * AST + c4 + 1] = cvt_tf32(vv.y);
            VS[key * AST + c4 + 2] = cvt_tf32(vv.z);
            VS[key * AST + c4 + 3] = cvt_tf32(vv.w);
        }
        __syncthreads();

        float4 s[8];
        #pragma unroll
        for (int j = 0; j < 8; j++) s[j] = make_float4(0.f, 0.f, 0.f, 0.f);
        #pragma unroll
        for (int kk = 0; kk < DH; kk += 8) {
            const int i0 = (rb + gid) * AST + kk + tig;
            const int i1 = (rb + gid + 8) * AST + kk + tig;
            const uint32_t a0 = QS[i0], a1 = QS[i1];
            const uint32_t a2 = QS[i0 + 4], a3 = QS[i1 + 4];
            #pragma unroll
            for (int j = 0; j < 8; j++) {
                const int bi = (j * 8 + gid) * AST + kk + tig;
                mma8(s[j].x, s[j].y, s[j].z, s[j].w,
                     a0, a1, a2, a3, KS[bi], KS[bi + 4]);
            }
        }

        float mt0 = -3.0e38f, mt1 = -3.0e38f;
        #pragma unroll
        for (int j = 0; j < 8; j++) {
            mt0 = fmaxf(mt0, fmaxf(s[j].x, s[j].y));
            mt1 = fmaxf(mt1, fmaxf(s[j].z, s[j].w));
        }
        mt0 = fmaxf(mt0, __shfl_xor_sync(0xffffffffu, mt0, 1));
        mt0 = fmaxf(mt0, __shfl_xor_sync(0xffffffffu, mt0, 2));
        mt1 = fmaxf(mt1, __shfl_xor_sync(0xffffffffu, mt1, 1));
        mt1 = fmaxf(mt1, __shfl_xor_sync(0xffffffffu, mt1, 2));
        const float mn0 = fmaxf(m0, mt0), mn1 = fmaxf(m1, mt1);
        const float al0 = __expf(m0 - mn0), al1 = __expf(m1 - mn1);
        m0 = mn0; m1 = mn1;

        float rs0 = 0.f, rs1 = 0.f;
        const int p0base = (rb + gid) * AST + tig * 2;
        const int p1base = (rb + gid + 8) * AST + tig * 2;
        #pragma unroll
        for (int j = 0; j < 8; j++) {
            const float e0 = __expf(s[j].x - mn0);
            const float e1 = __expf(s[j].y - mn0);
            const float e2 = __expf(s[j].z - mn1);
            const float e3 = __expf(s[j].w - mn1);
            rs0 += e0 + e1; rs1 += e2 + e3;
            PS[p0base + j * 8 + 0] = cvt_tf32(e0);
            PS[p0base + j * 8 + 1] = cvt_tf32(e1);
            PS[p1base + j * 8 + 0] = cvt_tf32(e2);
            PS[p1base + j * 8 + 1] = cvt_tf32(e3);
        }
        rs0 += __shfl_xor_sync(0xffffffffu, rs0, 1);
        rs0 += __shfl_xor_sync(0xffffffffu, rs0, 2);
        rs1 += __shfl_xor_sync(0xffffffffu, rs1, 1);
        rs1 += __shfl_xor_sync(0xffffffffu, rs1, 2);
        l0 = l0 * al0 + rs0;
        l1 = l1 * al1 + rs1;

        #pragma unroll
        for (int j = 0; j < 8; j++) {
            o[j].x *= al0; o[j].y *= al0;
            o[j].z *= al1; o[j].w *= al1;
        }
        __syncwarp();

        #pragma unroll
        for (int kk = 0; kk < BC; kk += 8) {
            const int i0 = (rb + gid) * AST + kk + tig;
            const int i1 = (rb + gid + 8) * AST + kk + tig;
            const uint32_t a0 = PS[i0], a1 = PS[i1];
            const uint32_t a2 = PS[i0 + 4], a3 = PS[i1 + 4];
            #pragma unroll
            for (int j = 0; j < 8; j++) {
                mma8(o[j].x, o[j].y, o[j].z, o[j].w,
                     a0, a1, a2, a3,
                     VS[(kk + tig) * AST + j * 8 + gid],
                     VS[(kk + tig + 4) * AST + j * 8 + gid]);
            }
        }
    }

    const int bb = bh / HEADS;
    const int head = bh % HEADS;
    const float inv0 = 1.0f / l0, inv1 = 1.0f / l1;
    const int n0 = qt * 128 + rb + gid;
    const int n1 = n0 + 8;
    float* dst0 = g_att + (size_t)(bb * SEQ + n0) * DIM + head * DH;
    float* dst1 = g_att + (size_t)(bb * SEQ + n1) * DIM + head * DH;
    #pragma unroll
    for (int j = 0; j < 8; j++) {
        const int col = j * 8 + tig * 2;
        dst0[col + 0] = o[j].x * inv0;
        dst0[col + 1] = o[j].y * inv0;
        dst1[col + 0] = o[j].z * inv1;
        dst1[col + 1] = o[j].w * inv1;
    }
}

// ---------------------------------------------------------------------------
// Launch
// ---------------------------------------------------------------------------
extern "C" void kernel_launch(void* const* d_in, const int* in_sizes, int n_in,
                              void* d_out, int out_size)
{
    const float* x     = (const float*)d_in[0];
    const float* w_qkv = (const float*)d_in[1];
    const float* b_qkv = (const float*)d_in[2];
    const float* w_out = (const float*)d_in[3];
    const float* b_out = (const float*)d_in[4];
    float* out = (float*)d_out;

    cudaFuncSetAttribute(attn_kernel,
                         cudaFuncAttributeMaxDynamicSharedMemorySize, ATTN_SMEM);

    // 1) QKV projection (split-bf16 tensor cores, scatter to [b,h,n,d])
    dim3 g1(3 * DIM / 64, MROWS / 128);   // (36, 64)
    gemm_qkv_bf16<<<g1, 256>>>(x, w_qkv, b_qkv);

    // 2) Flash attention (tf32 tensor cores)
    dim3 g2(BATCH * HEADS, SEQ / 128);    // (48, 16)
    attn_kernel<<<g2, 256, ATTN_SMEM>>>();

    // 3) Output projection (split-bf16 tensor cores; A = g_att internally)
    dim3 g3(DIM / 64, MROWS / 128);       // (12, 64)
    gemm_out_bf16<<<g3, 256>>>(w_out, b_out, out);
}